// round 15
// baseline (speedup 1.0000x reference)
#include <cuda_runtime.h>
#include <cuda_bf16.h>
#include <math.h>

#define TABLE_NUM 16
#define STYLE_DIM 512
#define CH 32
#define CMID 128
#define BATCH 8
#define NPIX 65536
#define PRIME 2654435761u
#define PDIM 258
#define PPIX (PDIM*PDIM)

typedef unsigned long long u64;
typedef unsigned int u32;

struct ResArr { int r[16]; };

__device__ float g_tok[(size_t)BATCH * CH * NPIX];
__device__ u32 g_xa1[(size_t)BATCH * PPIX * 32];    // padded [xh16|xl16] u32/px
__device__ u32 g_xa2[(size_t)BATCH * PPIX * 128];   // padded [xh64|xl64] u32/px
__device__ u32 g_w1e[3 * 9 * 128 * 16];             // seg0,1=wh seg2=wl
__device__ u32 g_w2e[3 * 9 * 32 * 64];
__device__ float g_st1[BATCH * CH];
__device__ float g_st2[BATCH * CMID];
__device__ float g_d1 [BATCH * CMID];
__device__ float g_d2 [BATCH * CH];

__device__ __forceinline__ float bfround(float v) {
    return __bfloat162float(__float2bfloat16_rn(v));
}
__device__ __forceinline__ u32 packbf(float lo, float hi) {
    u32 l = (u32)__bfloat16_as_ushort(__float2bfloat16_rn(lo));
    u32 h = (u32)__bfloat16_as_ushort(__float2bfloat16_rn(hi));
    return l | (h << 16);
}
__device__ __forceinline__ void mma16816(float* c, u32 a0, u32 a1, u32 a2, u32 a3,
                                         u32 b0, u32 b1) {
    asm volatile(
        "mma.sync.aligned.m16n8k16.row.col.f32.bf16.bf16.f32 "
        "{%0,%1,%2,%3}, {%4,%5,%6,%7}, {%8,%9}, {%0,%1,%2,%3};"
        : "+f"(c[0]), "+f"(c[1]), "+f"(c[2]), "+f"(c[3])
        : "r"(a0), "r"(a1), "r"(a2), "r"(a3), "r"(b0), "r"(b1));
}
__device__ __forceinline__ void ldsm4(u32& r0, u32& r1, u32& r2, u32& r3, u32 addr) {
    asm volatile("ldmatrix.sync.aligned.m8n8.x4.shared.b16 {%0,%1,%2,%3}, [%4];"
                 : "=r"(r0), "=r"(r1), "=r"(r2), "=r"(r3) : "r"(addr));
}
__device__ __forceinline__ u32 smem_u32(const void* p) {
    return (u32)__cvta_generic_to_shared(p);
}
__device__ __forceinline__ void cpasync16(u32 dst, const void* src) {
    asm volatile("cp.async.cg.shared.global [%0], [%1], 16;" :: "r"(dst), "l"(src));
}
__device__ __forceinline__ void cp_commit() {
    asm volatile("cp.async.commit_group;" ::: "memory");
}
__device__ __forceinline__ void cp_wait0() {
    asm volatile("cp.async.wait_group 0;" ::: "memory");
}
__device__ __forceinline__ void red2(float* p, float a, float b) {
    asm volatile("red.global.add.v2.f32 [%0], {%1, %2};"
                 :: "l"(p), "f"(a), "f"(b) : "memory");
}

__global__ void styles_kernel(const float* __restrict__ s,
                              const float* __restrict__ w1a, const float* __restrict__ b1a,
                              const float* __restrict__ w2a, const float* __restrict__ b2a)
{
    int b = blockIdx.x, t = threadIdx.x;
    float inv = 1.0f / sqrtf(512.0f);
    const float* sb = s + b * STYLE_DIM;
    if (t < CH) {
        float acc = 0.f;
        for (int k = 0; k < STYLE_DIM; ++k) acc += sb[k] * (w1a[k * CH + t] * inv);
        g_st1[b * CH + t] = acc + b1a[t];
    } else {
        int c = t - CH;
        float acc = 0.f;
        for (int k = 0; k < STYLE_DIM; ++k) acc += sb[k] * (w2a[k * CMID + c] * inv);
        g_st2[b * CMID + c] = acc + b2a[c];
    }
}

// merged: demod (blocks 0-5) | weight split (6-437) | borders (438+)
__global__ void util_kernel(const float* __restrict__ w1, const float* __restrict__ w2)
{
    int blk = blockIdx.x;
    if (blk < 6) {
        int i = blk * 256 + threadIdx.x;
        if (i < BATCH * CMID) {
            int b = i >> 7, o = i & 127;
            float acc = 0.f;
            for (int c = 0; c < CH; ++c) {
                float st = g_st1[b * CH + c], wq = 0.f;
                const float* wp = w1 + ((size_t)o * CH + c) * 9;
                #pragma unroll
                for (int t = 0; t < 9; ++t) { float v = wp[t]; wq += v * v; }
                acc += wq * st * st;
            }
            g_d1[i] = rsqrtf(acc + 1e-8f);
        } else if (i < BATCH * CMID + BATCH * CH) {
            int j = i - BATCH * CMID;
            int b = j >> 5, o = j & 31;
            float acc = 0.f;
            for (int c = 0; c < CMID; ++c) {
                float st = g_st2[b * CMID + c], wq = 0.f;
                const float* wp = w2 + ((size_t)o * CMID + c) * 9;
                #pragma unroll
                for (int t = 0; t < 9; ++t) { float v = wp[t]; wq += v * v; }
                acc += wq * st * st;
            }
            g_d2[j] = rsqrtf(acc + 1e-8f);
        }
    } else if (blk < 438) {
        int i = (blk - 6) * 256 + threadIdx.x;
        if (i < 3 * 9 * 128 * 16) {
            int j = i & 15, rest = i >> 4;
            int o = rest & 127; rest >>= 7;
            int t = rest % 9, s = rest / 9;
            float va = w1[((size_t)o * 32 + 2 * j) * 9 + t];
            float vb = w1[((size_t)o * 32 + 2 * j + 1) * 9 + t];
            if (s == 2) { va -= bfround(va); vb -= bfround(vb); }
            g_w1e[i] = packbf(va, vb);
        } else {
            int i2 = i - 3 * 9 * 128 * 16;
            if (i2 < 3 * 9 * 32 * 64) {
                int j = i2 & 63, rest = i2 >> 6;
                int o = rest & 31; rest >>= 5;
                int t = rest % 9, s = rest / 9;
                float va = w2[((size_t)o * 128 + 2 * j) * 9 + t];
                float vb = w2[((size_t)o * 128 + 2 * j + 1) * 9 + t];
                if (s == 2) { va -= bfround(va); vb -= bfround(vb); }
                g_w2e[i2] = packbf(va, vb);
            }
        }
    } else {
        int cell = blk - 438;
        int b = cell / 1032, e = cell % 1032;
        int gy, gx;
        if      (e < 258) { gy = 0;       gx = e; }
        else if (e < 516) { gy = 257;     gx = e - 258; }
        else if (e < 774) { gy = e - 516; gx = 0; }
        else              { gy = e - 774; gx = 257; }
        size_t p = (size_t)b * PPIX + (size_t)gy * PDIM + gx;
        int t = threadIdx.x;
        if (t < 32)       g_xa1[p * 32 + t] = 0u;
        else if (t < 160) g_xa2[p * 128 + (t - 32)] = 0u;
    }
}

// retrieve fused with split: writes padded split-bf16 rows of g_xa1 directly
__global__ void __launch_bounds__(256) retrieve_kernel(
    const float* __restrict__ tables, const float* __restrict__ coords, ResArr R)
{
    int idx = blockIdx.x * 256 + threadIdx.x;
    int b = idx >> 16, p = idx & 65535;
    __shared__ float s1[CH];
    if (threadIdx.x < CH) s1[threadIdx.x] = g_st1[b * CH + threadIdx.x];
    __syncthreads();
    float cx = coords[((size_t)b * NPIX + p) * 2 + 0];
    float cy = coords[((size_t)b * NPIX + p) * 2 + 1];
    u32 ov[32];
    #pragma unroll
    for (int l = 0; l < 16; ++l) {
        float rf = (float)R.r[l];
        float px = cx * rf, py = cy * rf;
        float fx0 = floorf(px), fy0 = floorf(py);
        float fx = px - fx0, fy = py - fy0;
        unsigned x0 = (unsigned)fx0, y0 = (unsigned)fy0;
        unsigned hy0 = y0 * PRIME, hy1 = (y0 + 1u) * PRIME;
        unsigned h00 = (x0 ^ hy0) & 65535u, h10 = ((x0 + 1u) ^ hy0) & 65535u;
        unsigned h01 = (x0 ^ hy1) & 65535u, h11 = ((x0 + 1u) ^ hy1) & 65535u;
        const float2* tab = reinterpret_cast<const float2*>(tables) + ((size_t)(b * 16 + l) << 16);
        float2 f00 = __ldg(tab + h00), f10 = __ldg(tab + h10);
        float2 f01 = __ldg(tab + h01), f11 = __ldg(tab + h11);
        float w00 = (1.f - fx) * (1.f - fy), w10 = fx * (1.f - fy);
        float w01 = (1.f - fx) * fy,         w11 = fx * fy;
        float e0 = (w00 * f00.x + w10 * f10.x + w01 * f01.x + w11 * f11.x) * s1[2 * l];
        float e1 = (w00 * f00.y + w10 * f10.y + w01 * f01.y + w11 * f11.y) * s1[2 * l + 1];
        ov[l]      = packbf(e0, e1);
        ov[16 + l] = packbf(e0 - bfround(e0), e1 - bfround(e1));
    }
    int gy = p >> 8, gx = p & 255;
    u32* row = g_xa1 + ((size_t)b * PPIX + (size_t)(gy + 1) * PDIM + gx + 1) * 32;
    #pragma unroll
    for (int j = 0; j < 8; ++j)
        *reinterpret_cast<uint4*>(row + 4 * j) =
            make_uint4(ov[4 * j], ov[4 * j + 1], ov[4 * j + 2], ov[4 * j + 3]);
}

// ---------------------------------------------------------------------------
// conv1: implicit-GEMM mma.sync, 3-term split. A resident for BOTH segments
// (pitch 36 u32, [xh16|xl16] per row, staged once). B staged 3 taps/group,
// double-buffered cp.async -> 9 coarse iterations, 9 barriers total.
// ---------------------------------------------------------------------------
__global__ void __launch_bounds__(256, 2) conv1_kernel(const float* __restrict__ bias)
{
    constexpr int AP   = 36;                  // A pitch u32 (144B; LDSM-safe)
    constexpr int BP   = 20;
    constexpr int ASZ  = 340 * AP;            // 12240 u32
    constexpr int BTAP = 64 * BP;             // 1280 u32
    constexpr int BGRP = 3 * BTAP;            // 3840 u32
    constexpr int DP   = 68;

    extern __shared__ float smf[];
    u32* sA = reinterpret_cast<u32*>(smf);
    float* sD = smf;
    __shared__ float s_d[64], s_b[64], s_m[64];

    int zz = blockIdx.z;
    int bb = zz >> 1, og = zz & 1;
    int gy0 = blockIdx.y * 8, gx0 = blockIdx.x * 32;
    int tid = threadIdx.x;
    int w = tid >> 5, lane = tid & 31, g = lane >> 2, tig = lane & 3;
    int qrow = w >> 1;
    int lane7 = lane & 7, l8 = (lane >> 3) & 1, l16 = (lane >> 4) & 1;

    if (tid < 64) {
        s_d[tid] = g_d1[bb * 128 + og * 64 + tid];
        s_b[tid] = bias[og * 64 + tid];
        s_m[tid] = g_st2[bb * CMID + og * 64 + tid] * 1.4142135623730951f;
    }

    u32 saBase = smem_u32(sA);
    u32 sbB[2] = { smem_u32(sA + ASZ), smem_u32(sA + ASZ + BGRP) };
    int arow0 = qrow * 34 + (w & 1) * 16 + lane7 + l8 * 8;
    u32 akoff = (u32)(l16 * 16);
    int brow = lane7 + l16 * 8;
    u32 bkoff = (u32)(l8 * 16);

    size_t abase = (size_t)bb * PPIX;
    float acc[2][8][4];
    #pragma unroll
    for (int rb = 0; rb < 2; ++rb)
        #pragma unroll
        for (int n = 0; n < 8; ++n)
            #pragma unroll
            for (int q = 0; q < 4; ++q) acc[rb][n][q] = 0.f;

    // stage A: full rows (both segments), once
    for (int i = tid; i < 340 * 8; i += 256) {
        int r = i >> 3, w4 = i & 7;
        int sy = r / 34, sx = r - sy * 34;
        size_t p = abase + (size_t)(gy0 + sy) * PDIM + gx0 + sx;
        uint4 v = *reinterpret_cast<const uint4*>(g_xa1 + p * 32 + w4 * 4);
        *reinterpret_cast<uint4*>(sA + r * AP + w4 * 4) = v;
    }
    // B group stage (3 taps) via cp.async
    auto issueB = [&](int grp) {
        int si = grp / 3, tg = grp - 3 * si;
        int s = (si == 0) ? 0 : (si == 1) ? 2 : 1;   // wh(xh), wl(xh), wh(xl)
        u32 dstb = sbB[grp & 1];
        for (int i = tid; i < 3 * 64 * 4; i += 256) {
            int t3 = i >> 8, r = i & 255;
            int o = r >> 2, w4 = r & 3;
            cpasync16(dstb + (u32)(((t3 * 64 + o) * BP + w4 * 4) * 4),
                      g_w1e + ((size_t)((s * 9 + tg * 3 + t3) * 128 + og * 64 + o)) * 16 + w4 * 4);
        }
        cp_commit();
    };
    issueB(0);

    #pragma unroll 1
    for (int grp = 0; grp < 9; ++grp) {
        cp_wait0();
        __syncthreads();
        if (grp < 8) issueB(grp + 1);
        int si = grp / 3, tg = grp - 3 * si;
        u32 segU = (si == 2) ? 16u : 0u;
        u32 sbCur = sbB[grp & 1];
        #pragma unroll
        for (int t3 = 0; t3 < 3; ++t3) {
            int arow = arow0 + tg * 34 + t3;
            u32 aAddr = saBase + (u32)(arow * AP + (int)segU) * 4u + akoff;
            u32 bTap = sbCur + (u32)(t3 * BTAP * 4);
            #pragma unroll
            for (int kc = 0; kc < 2; ++kc) {
                u32 a[2][4];
                ldsm4(a[0][0], a[0][1], a[0][2], a[0][3], aAddr + (u32)(kc * 32));
                ldsm4(a[1][0], a[1][1], a[1][2], a[1][3],
                      aAddr + (u32)(kc * 32) + (u32)(136 * AP * 4));
                #pragma unroll
                for (int j = 0; j < 4; ++j) {
                    u32 b0, b1, b2, b3;
                    u32 bAddr = bTap + (u32)(((j * 16 + brow) * BP + kc * 8) * 4) + bkoff;
                    ldsm4(b0, b1, b2, b3, bAddr);
                    mma16816(acc[0][2 * j],     a[0][0], a[0][1], a[0][2], a[0][3], b0, b1);
                    mma16816(acc[0][2 * j + 1], a[0][0], a[0][1], a[0][2], a[0][3], b2, b3);
                    mma16816(acc[1][2 * j],     a[1][0], a[1][1], a[1][2], a[1][3], b0, b1);
                    mma16816(acc[1][2 * j + 1], a[1][0], a[1][1], a[1][2], a[1][3], b2, b3);
                }
            }
        }
    }

    #pragma unroll 1
    for (int rb = 0; rb < 2; ++rb) {
        __syncthreads();
        int q0 = w * 16 + g;
        #pragma unroll
        for (int nf = 0; nf < 8; ++nf) {
            int cb = nf * 8 + 2 * tig;
            float d0 = s_d[cb], d1 = s_d[cb + 1];
            float b0 = s_b[cb], b1 = s_b[cb + 1];
            float m0 = s_m[cb], m1 = s_m[cb + 1];
            float y00 = acc[rb][nf][0] * d0 + b0, y01 = acc[rb][nf][1] * d1 + b1;
            float y10 = acc[rb][nf][2] * d0 + b0, y11 = acc[rb][nf][3] * d1 + b1;
            y00 = (y00 < 0.f ? 0.2f * y00 : y00) * m0;
            y01 = (y01 < 0.f ? 0.2f * y01 : y01) * m1;
            y10 = (y10 < 0.f ? 0.2f * y10 : y10) * m0;
            y11 = (y11 < 0.f ? 0.2f * y11 : y11) * m1;
            sD[q0 * DP + cb] = y00; sD[q0 * DP + cb + 1] = y01;
            sD[(q0 + 8) * DP + cb] = y10; sD[(q0 + 8) * DP + cb + 1] = y11;
        }
        __syncthreads();
        for (int i = tid; i < 128 * 16; i += 256) {
            int q = i >> 4, t = i & 15;
            float4 y = *reinterpret_cast<const float4*>(sD + q * DP + 4 * t);
            u32 xh0 = packbf(y.x, y.y), xh1 = packbf(y.z, y.w);
            u32 xl0 = packbf(y.x - bfround(y.x), y.y - bfround(y.y));
            u32 xl1 = packbf(y.z - bfround(y.z), y.w - bfround(y.w));
            int gy = gy0 + rb * 4 + (q >> 5), gx = gx0 + (q & 31);
            u32* row = g_xa2 + (abase + (size_t)(gy + 1) * PDIM + gx + 1) * 128;
            int wj = og * 32 + 2 * t;
            *reinterpret_cast<u64*>(row + wj)      = (u64)xh0 | ((u64)xh1 << 32);
            *reinterpret_cast<u64*>(row + 64 + wj) = (u64)xl0 | ((u64)xl1 << 32);
        }
    }
}

// conv2: proven R14 (depth-1 cp.async double buffer)
__global__ void __launch_bounds__(256, 2) conv2_kernel(const float* __restrict__ bias)
{
    constexpr int KSEG = 64, KROW = 128;
    constexpr int AP = 68, BP = 68;
    constexpr int KC = 8, NF = 4, DP = 36;
    constexpr int ASZ = 340 * AP, BSZ = 32 * BP;

    extern __shared__ float smf[];
    u32* sA = reinterpret_cast<u32*>(smf);
    u32* sB0 = sA + ASZ;
    u32* sB1 = sA + ASZ + BSZ;
    float* sD = smf;
    __shared__ float s_d[32], s_b[32];

    int bb = blockIdx.z;
    int gy0 = blockIdx.y * 8, gx0 = blockIdx.x * 32;
    int tid = threadIdx.x;
    int w = tid >> 5, lane = tid & 31, g = lane >> 2, tig = lane & 3;
    int qrow = w >> 1;
    int lane7 = lane & 7, l8 = (lane >> 3) & 1, l16 = (lane >> 4) & 1;

    if (tid < 32) {
        s_d[tid] = g_d2[bb * 32 + tid];
        s_b[tid] = bias[tid];
    }

    u32 saBase = smem_u32(sA);
    u32 sbB[2] = { smem_u32(sB0), smem_u32(sB1) };
    int arow0 = qrow * 34 + (w & 1) * 16 + lane7 + l8 * 8;
    u32 akoff = (u32)(l16 * 16);
    int brow = lane7 + l16 * 8;
    u32 bkoff = (u32)(l8 * 16);

    size_t abase = (size_t)bb * PPIX;
    float acc[2][NF][4];
    #pragma unroll
    for (int rb = 0; rb < 2; ++rb)
        #pragma unroll
        for (int n = 0; n < NF; ++n)
            #pragma unroll
            for (int q = 0; q < 4; ++q) acc[rb][n][q] = 0.f;

    auto stageA = [&](int segoff) {
        for (int i = tid; i < 340 * (KSEG / 4); i += 256) {
            int r = i / (KSEG / 4), w4 = i - r * (KSEG / 4);
            int sy = r / 34, sx = r - sy * 34;
            size_t p = abase + (size_t)(gy0 + sy) * PDIM + gx0 + sx;
            uint4 v = *reinterpret_cast<const uint4*>(g_xa2 + p * KROW + segoff + w4 * 4);
            *reinterpret_cast<uint4*>(sA + r * AP + w4 * 4) = v;
        }
    };
    auto issueB = [&](int it2) {
        int si2 = it2 / 9, tap2 = it2 - 9 * si2;
        int s2 = (si2 == 0) ? 0 : (si2 == 1) ? 2 : 1;
        u32 dstb = sbB[it2 & 1];
        const u32* src = g_w2e + ((size_t)((s2 * 9 + tap2) * 32)) * KSEG;
        for (int i = tid; i < 32 * (KSEG / 4); i += 256) {
            int o = i / (KSEG / 4), w4 = i - o * (KSEG / 4);
            cpasync16(dstb + (u32)((o * BP + w4 * 4) * 4), src + (size_t)o * KSEG + w4 * 4);
        }
        cp_commit();
    };

    stageA(0);
    issueB(0);

    #pragma unroll 1
    for (int it = 0; it < 27; ++it) {
        cp_wait0();
        __syncthreads();
        if (it == 18) stageA(KSEG);
        if (it < 26) issueB(it + 1);
        if (it == 18) __syncthreads();
        int si = it / 9, tap = it - 9 * si;
        int ty = tap / 3, tx = tap - 3 * ty;
        int arow = arow0 + ty * 34 + tx;
        u32 aAddr = saBase + (u32)(arow * AP) * 4u + akoff;
        u32 sbCur = sbB[it & 1];
        #pragma unroll
        for (int kc = 0; kc < KC; ++kc) {
            u32 a[2][4];
            ldsm4(a[0][0], a[0][1], a[0][2], a[0][3], aAddr + (u32)(kc * 32));
            ldsm4(a[1][0], a[1][1], a[1][2], a[1][3],
                  aAddr + (u32)(kc * 32) + (u32)(136 * AP * 4));
            #pragma unroll
            for (int j = 0; j < NF / 2; ++j) {
                u32 b0, b1, b2, b3;
                u32 bAddr = sbCur + (u32)(((j * 16 + brow) * BP + kc * 8) * 4) + bkoff;
                ldsm4(b0, b1, b2, b3, bAddr);
                mma16816(acc[0][2 * j],     a[0][0], a[0][1], a[0][2], a[0][3], b0, b1);
                mma16816(acc[0][2 * j + 1], a[0][0], a[0][1], a[0][2], a[0][3], b2, b3);
                mma16816(acc[1][2 * j],     a[1][0], a[1][1], a[1][2], a[1][3], b0, b1);
                mma16816(acc[1][2 * j + 1], a[1][0], a[1][1], a[1][2], a[1][3], b2, b3);
            }
        }
    }

    #pragma unroll 1
    for (int rb = 0; rb < 2; ++rb) {
        __syncthreads();
        int q0 = w * 16 + g;
        #pragma unroll
        for (int nf = 0; nf < NF; ++nf) {
            int cb = nf * 8 + 2 * tig;
            float d0 = s_d[cb], d1 = s_d[cb + 1];
            float b0 = s_b[cb], b1 = s_b[cb + 1];
            sD[q0 * DP + cb]       = acc[rb][nf][0] * d0 + b0;
            sD[q0 * DP + cb + 1]   = acc[rb][nf][1] * d1 + b1;
            sD[(q0 + 8) * DP + cb]     = acc[rb][nf][2] * d0 + b0;
            sD[(q0 + 8) * DP + cb + 1] = acc[rb][nf][3] * d1 + b1;
        }
        __syncthreads();
        for (int i = tid; i < 32 * 128; i += 256) {
            int c = i >> 7, q = i & 127;
            float v = sD[q * DP + c];
            int gy = gy0 + rb * 4 + (q >> 5), gx = gx0 + (q & 31);
            g_tok[((size_t)bb * CH + c) * NPIX + gy * 256 + gx] = v;
        }
    }
}

// ---------------------------------------------------------------------------
// Recon: row-separable, atomic-free gather-by-column (proven R14).
// ---------------------------------------------------------------------------
__global__ void __launch_bounds__(256) recon_kernel(
    const float* __restrict__ coords, float* __restrict__ out, ResArr R)
{
    __shared__ float smv0[256], smv1[256], smcx[256];
    int j = blockIdx.x & 255, b = blockIdx.x >> 8;
    int i = threadIdx.x;
    size_t pbase = (size_t)b * NPIX + (size_t)j * 256;
    smcx[i] = coords[(pbase + i) * 2 + 0];
    float cy = coords[pbase * 2 + 1];          // constant across the row

    #pragma unroll 1
    for (int l = 0; l < 16; ++l) {
        int Rl = R.r[l];
        float rf = (float)Rl;
        __syncthreads();
        smv0[i] = g_tok[(((size_t)(b * 32 + 2 * l))     << 16) + j * 256 + i];
        smv1[i] = g_tok[(((size_t)(b * 32 + 2 * l + 1)) << 16) + j * 256 + i];
        __syncthreads();
        float py = cy * rf;
        float fl = floorf(py);
        float fy = py - fl;
        u32 y0 = (u32)fl;
        u32 hy0 = y0 * PRIME, hy1 = (y0 + 1u) * PRIME;
        float wy0 = 1.f - fy;
        float* ob = out + ((size_t)(b * 16 + l) << 17);
        for (int k = i; k <= Rl; k += 256) {
            int lo = (int)((k - 1) * 256.f / rf) - 2; if (lo < 0) lo = 0;
            int hi = (int)((k + 1) * 256.f / rf) + 2; if (hi > 255) hi = 255;
            float t0 = 0.f, t1 = 0.f;
            for (int ii = lo; ii <= hi; ++ii) {
                float px = smcx[ii] * rf;
                float f0 = floorf(px);
                int x0 = (int)f0;
                float fx = px - f0;
                float wv = (x0 == k) ? (1.f - fx) : ((x0 == k - 1) ? fx : 0.f);
                t0 += wv * smv0[ii];
                t1 += wv * smv1[ii];
            }
            u32 h0 = ((u32)k ^ hy0) & 65535u;
            u32 h1 = ((u32)k ^ hy1) & 65535u;
            red2(ob + 2 * h0, wy0 * t0, wy0 * t1);
            red2(ob + 2 * h1, fy * t0,  fy * t1);
        }
    }
}

extern "C" void kernel_launch(void* const* d_in, const int* in_sizes, int n_in,
                              void* d_out, int out_size)
{
    const float* inputs = (const float*)d_in[0];
    const float* s      = (const float*)d_in[1];
    const float* coords = (const float*)d_in[2];
    const float* w1_aff = (const float*)d_in[3];
    const float* b1_aff = (const float*)d_in[4];
    const float* w1     = (const float*)d_in[5];
    const float* b1     = (const float*)d_in[6];
    const float* w2_aff = (const float*)d_in[7];
    const float* b2_aff = (const float*)d_in[8];
    const float* w2     = (const float*)d_in[9];
    const float* b2     = (const float*)d_in[10];
    float* out = (float*)d_out;

    ResArr R;
    double bb = exp((log(256.0) - log(16.0)) / 15.0);
    for (int l = 0; l < 16; ++l)
        R.r[l] = (int)floor(16.0 * pow(bb, (double)l));

    const int SM1 = (340 * 36 + 2 * 3 * 64 * 20) * 4;   // 79680
    const int SM2 = (340 * 68 + 2 * 32 * 68) * 4;       // 109888
    cudaFuncSetAttribute(conv1_kernel, cudaFuncAttributeMaxDynamicSharedMemorySize, SM1);
    cudaFuncSetAttribute(conv2_kernel, cudaFuncAttributeMaxDynamicSharedMemorySize, SM2);

    cudaMemsetAsync(d_out, 0, (size_t)out_size * sizeof(float));

    styles_kernel<<<BATCH, CH + CMID>>>(s, w1_aff, b1_aff, w2_aff, b2_aff);
    util_kernel<<<438 + BATCH * 1032, 256>>>(w1, w2);
    retrieve_kernel<<<(BATCH * NPIX) / 256, 256>>>(inputs, coords, R);

    dim3 cg1(8, 32, BATCH * 2);
    conv1_kernel<<<cg1, 256, SM1>>>(b1);
    dim3 cg2(8, 32, BATCH);
    conv2_kernel<<<cg2, 256, SM2>>>(b2);

    recon_kernel<<<BATCH * 256, 256>>>(coords, out, R);
}

// round 16
// speedup vs baseline: 1.0829x; 1.0829x over previous
#include <cuda_runtime.h>
#include <cuda_bf16.h>
#include <math.h>

#define TABLE_NUM 16
#define STYLE_DIM 512
#define CH 32
#define CMID 128
#define BATCH 8
#define NPIX 65536
#define PRIME 2654435761u
#define PDIM 258
#define PPIX (PDIM*PDIM)

typedef unsigned long long u64;
typedef unsigned int u32;

struct ResArr { int r[16]; };

__device__ float g_tok[(size_t)BATCH * CH * NPIX];
__device__ u32 g_xa1[(size_t)BATCH * PPIX * 32];    // padded [xh16|xl16] u32/px
__device__ u32 g_xa2[(size_t)BATCH * PPIX * 128];   // padded [xh64|xl64] u32/px
__device__ u32 g_w1e[3 * 9 * 128 * 16];             // seg0,1=wh seg2=wl
__device__ u32 g_w2e[3 * 9 * 32 * 64];
__device__ float g_st1[BATCH * CH];
__device__ float g_st2[BATCH * CMID];
__device__ float g_d1 [BATCH * CMID];
__device__ float g_d2 [BATCH * CH];

__device__ __forceinline__ float bfround(float v) {
    return __bfloat162float(__float2bfloat16_rn(v));
}
__device__ __forceinline__ u32 packbf(float lo, float hi) {
    u32 l = (u32)__bfloat16_as_ushort(__float2bfloat16_rn(lo));
    u32 h = (u32)__bfloat16_as_ushort(__float2bfloat16_rn(hi));
    return l | (h << 16);
}
__device__ __forceinline__ void mma16816(float* c, u32 a0, u32 a1, u32 a2, u32 a3,
                                         u32 b0, u32 b1) {
    asm volatile(
        "mma.sync.aligned.m16n8k16.row.col.f32.bf16.bf16.f32 "
        "{%0,%1,%2,%3}, {%4,%5,%6,%7}, {%8,%9}, {%0,%1,%2,%3};"
        : "+f"(c[0]), "+f"(c[1]), "+f"(c[2]), "+f"(c[3])
        : "r"(a0), "r"(a1), "r"(a2), "r"(a3), "r"(b0), "r"(b1));
}
__device__ __forceinline__ void ldsm4(u32& r0, u32& r1, u32& r2, u32& r3, u32 addr) {
    asm volatile("ldmatrix.sync.aligned.m8n8.x4.shared.b16 {%0,%1,%2,%3}, [%4];"
                 : "=r"(r0), "=r"(r1), "=r"(r2), "=r"(r3) : "r"(addr));
}
__device__ __forceinline__ u32 smem_u32(const void* p) {
    return (u32)__cvta_generic_to_shared(p);
}
__device__ __forceinline__ void cpasync16(u32 dst, const void* src) {
    asm volatile("cp.async.cg.shared.global [%0], [%1], 16;" :: "r"(dst), "l"(src));
}
__device__ __forceinline__ void cp_commit() {
    asm volatile("cp.async.commit_group;" ::: "memory");
}
__device__ __forceinline__ void cp_wait0() {
    asm volatile("cp.async.wait_group 0;" ::: "memory");
}
__device__ __forceinline__ void red2(float* p, float a, float b) {
    asm volatile("red.global.add.v2.f32 [%0], {%1, %2};"
                 :: "l"(p), "f"(a), "f"(b) : "memory");
}

// styles (blocks 0-7) | weight split (8-439) | borders (440+)
__global__ void styles_kernel(const float* __restrict__ s,
                              const float* __restrict__ w1a, const float* __restrict__ b1a,
                              const float* __restrict__ w2a, const float* __restrict__ b2a,
                              const float* __restrict__ w1,  const float* __restrict__ w2)
{
    int blk = blockIdx.x;
    if (blk < 8) {
        int b = blk, t = threadIdx.x;
        float inv = 1.0f / sqrtf(512.0f);
        const float* sb = s + b * STYLE_DIM;
        if (t < CH) {
            float acc = 0.f;
            for (int k = 0; k < STYLE_DIM; ++k) acc += sb[k] * (w1a[k * CH + t] * inv);
            g_st1[b * CH + t] = acc + b1a[t];
        } else if (t < CH + CMID) {
            int c = t - CH;
            float acc = 0.f;
            for (int k = 0; k < STYLE_DIM; ++k) acc += sb[k] * (w2a[k * CMID + c] * inv);
            g_st2[b * CMID + c] = acc + b2a[c];
        }
    } else if (blk < 440) {
        int i = (blk - 8) * 256 + threadIdx.x;
        if (i < 3 * 9 * 128 * 16) {
            int j = i & 15, rest = i >> 4;
            int o = rest & 127; rest >>= 7;
            int t = rest % 9, sI = rest / 9;
            float va = w1[((size_t)o * 32 + 2 * j) * 9 + t];
            float vb = w1[((size_t)o * 32 + 2 * j + 1) * 9 + t];
            if (sI == 2) { va -= bfround(va); vb -= bfround(vb); }
            g_w1e[i] = packbf(va, vb);
        } else {
            int i2 = i - 3 * 9 * 128 * 16;
            if (i2 < 3 * 9 * 32 * 64) {
                int j = i2 & 63, rest = i2 >> 6;
                int o = rest & 31; rest >>= 5;
                int t = rest % 9, sI = rest / 9;
                float va = w2[((size_t)o * 128 + 2 * j) * 9 + t];
                float vb = w2[((size_t)o * 128 + 2 * j + 1) * 9 + t];
                if (sI == 2) { va -= bfround(va); vb -= bfround(vb); }
                g_w2e[i2] = packbf(va, vb);
            }
        }
    } else {
        int cell = blk - 440;
        int b = cell / 1032, e = cell % 1032;
        int gy, gx;
        if      (e < 258) { gy = 0;       gx = e; }
        else if (e < 516) { gy = 257;     gx = e - 258; }
        else if (e < 774) { gy = e - 516; gx = 0; }
        else              { gy = e - 774; gx = 257; }
        size_t p = (size_t)b * PPIX + (size_t)gy * PDIM + gx;
        int t = threadIdx.x;
        if (t < 32)       g_xa1[p * 32 + t] = 0u;
        else if (t < 160) g_xa2[p * 128 + (t - 32)] = 0u;
    }
}

// retrieve (blocks 0-2047, fused with split) | demod (blocks 2048-2053)
__global__ void __launch_bounds__(256) retrieve_kernel(
    const float* __restrict__ tables, const float* __restrict__ coords,
    const float* __restrict__ w1, const float* __restrict__ w2, ResArr R)
{
    if (blockIdx.x >= 2048) {
        int i = (blockIdx.x - 2048) * 256 + threadIdx.x;
        if (i < BATCH * CMID) {
            int b = i >> 7, o = i & 127;
            float acc = 0.f;
            for (int c = 0; c < CH; ++c) {
                float st = g_st1[b * CH + c], wq = 0.f;
                const float* wp = w1 + ((size_t)o * CH + c) * 9;
                #pragma unroll
                for (int t = 0; t < 9; ++t) { float v = wp[t]; wq += v * v; }
                acc += wq * st * st;
            }
            g_d1[i] = rsqrtf(acc + 1e-8f);
        } else if (i < BATCH * CMID + BATCH * CH) {
            int j = i - BATCH * CMID;
            int b = j >> 5, o = j & 31;
            float acc = 0.f;
            for (int c = 0; c < CMID; ++c) {
                float st = g_st2[b * CMID + c], wq = 0.f;
                const float* wp = w2 + ((size_t)o * CMID + c) * 9;
                #pragma unroll
                for (int t = 0; t < 9; ++t) { float v = wp[t]; wq += v * v; }
                acc += wq * st * st;
            }
            g_d2[j] = rsqrtf(acc + 1e-8f);
        }
        return;
    }
    int idx = blockIdx.x * 256 + threadIdx.x;
    int b = idx >> 16, p = idx & 65535;
    __shared__ float s1[CH];
    if (threadIdx.x < CH) s1[threadIdx.x] = g_st1[b * CH + threadIdx.x];
    __syncthreads();
    float cx = coords[((size_t)b * NPIX + p) * 2 + 0];
    float cy = coords[((size_t)b * NPIX + p) * 2 + 1];
    u32 ov[32];
    #pragma unroll
    for (int l = 0; l < 16; ++l) {
        float rf = (float)R.r[l];
        float px = cx * rf, py = cy * rf;
        float fx0 = floorf(px), fy0 = floorf(py);
        float fx = px - fx0, fy = py - fy0;
        unsigned x0 = (unsigned)fx0, y0 = (unsigned)fy0;
        unsigned hy0 = y0 * PRIME, hy1 = (y0 + 1u) * PRIME;
        unsigned h00 = (x0 ^ hy0) & 65535u, h10 = ((x0 + 1u) ^ hy0) & 65535u;
        unsigned h01 = (x0 ^ hy1) & 65535u, h11 = ((x0 + 1u) ^ hy1) & 65535u;
        const float2* tab = reinterpret_cast<const float2*>(tables) + ((size_t)(b * 16 + l) << 16);
        float2 f00 = __ldg(tab + h00), f10 = __ldg(tab + h10);
        float2 f01 = __ldg(tab + h01), f11 = __ldg(tab + h11);
        float w00 = (1.f - fx) * (1.f - fy), w10 = fx * (1.f - fy);
        float w01 = (1.f - fx) * fy,         w11 = fx * fy;
        float e0 = (w00 * f00.x + w10 * f10.x + w01 * f01.x + w11 * f11.x) * s1[2 * l];
        float e1 = (w00 * f00.y + w10 * f10.y + w01 * f01.y + w11 * f11.y) * s1[2 * l + 1];
        ov[l]      = packbf(e0, e1);
        ov[16 + l] = packbf(e0 - bfround(e0), e1 - bfround(e1));
    }
    int gy = p >> 8, gx = p & 255;
    u32* row = g_xa1 + ((size_t)b * PPIX + (size_t)(gy + 1) * PDIM + gx + 1) * 32;
    #pragma unroll
    for (int j = 0; j < 8; ++j)
        *reinterpret_cast<uint4*>(row + 4 * j) =
            make_uint4(ov[4 * j], ov[4 * j + 1], ov[4 * j + 2], ov[4 * j + 3]);
}

// implicit-GEMM 3x3 conv on mma.sync + ldmatrix, 3-term bf16 split (proven R12).
template<int PASS>
__global__ void __launch_bounds__(256, 2) convmma_kernel(const float* __restrict__ bias)
{
    constexpr int COUT  = (PASS == 1) ? 128 : 32;
    constexpr int COUTB = (PASS == 1) ? 64  : 32;
    constexpr int KSEG  = (PASS == 1) ? 16  : 64;
    constexpr int KROW  = (PASS == 1) ? 32  : 128;
    constexpr int AP    = (PASS == 1) ? 20  : 68;
    constexpr int BP    = AP;
    constexpr int KC    = KSEG / 8;
    constexpr int NF    = COUTB / 8;
    constexpr int DP    = (PASS == 1) ? 68 : 36;
    constexpr int ASZ   = 340 * AP;
    constexpr int BSZ   = COUTB * BP;

    extern __shared__ float smf[];
    u32* sA = reinterpret_cast<u32*>(smf);
    u32* sB0 = sA + ASZ;
    u32* sB1 = sA + ASZ + BSZ;
    float* sD = smf;
    __shared__ float s_d[COUTB], s_b[COUTB], s_m[COUTB];

    const u32* gin = (PASS == 1) ? g_xa1 : g_xa2;
    const u32* we  = (PASS == 1) ? g_w1e : g_w2e;
    const float* dsc = (PASS == 1) ? g_d1 : g_d2;

    int zz = blockIdx.z;
    int bb = (PASS == 1) ? (zz >> 1) : zz;
    int og = (PASS == 1) ? (zz & 1)  : 0;
    int gy0 = blockIdx.y * 8, gx0 = blockIdx.x * 32;
    int tid = threadIdx.x;
    int w = tid >> 5, lane = tid & 31, g = lane >> 2, tig = lane & 3;
    int qrow = w >> 1;
    int lane7 = lane & 7, l8 = (lane >> 3) & 1, l16 = (lane >> 4) & 1;

    if (tid < COUTB) {
        s_d[tid] = dsc[bb * COUT + og * COUTB + tid];
        s_b[tid] = bias[og * COUTB + tid];
        s_m[tid] = (PASS == 1) ? g_st2[bb * CMID + og * COUTB + tid] * 1.4142135623730951f : 0.f;
    }

    u32 saBase = smem_u32(sA);
    u32 sbB[2] = { smem_u32(sB0), smem_u32(sB1) };
    int arow0 = qrow * 34 + (w & 1) * 16 + lane7 + l8 * 8;
    u32 akoff = (u32)(l16 * 16);
    int brow = lane7 + l16 * 8;
    u32 bkoff = (u32)(l8 * 16);

    size_t abase = (size_t)bb * PPIX;
    float acc[2][NF][4];
    #pragma unroll
    for (int rb = 0; rb < 2; ++rb)
        #pragma unroll
        for (int n = 0; n < NF; ++n)
            #pragma unroll
            for (int q = 0; q < 4; ++q) acc[rb][n][q] = 0.f;

    auto stageA = [&](int segoff) {
        for (int i = tid; i < 340 * (KSEG / 4); i += 256) {
            int r = i / (KSEG / 4), w4 = i - r * (KSEG / 4);
            int sy = r / 34, sx = r - sy * 34;
            size_t p = abase + (size_t)(gy0 + sy) * PDIM + gx0 + sx;
            uint4 v = *reinterpret_cast<const uint4*>(gin + p * KROW + segoff + w4 * 4);
            *reinterpret_cast<uint4*>(sA + r * AP + w4 * 4) = v;
        }
    };
    auto issueB = [&](int it2) {
        int si2 = it2 / 9, tap2 = it2 - 9 * si2;
        int s2 = (si2 == 0) ? 0 : (si2 == 1) ? 2 : 1;   // wh, wl, wh
        u32 dstb = sbB[it2 & 1];
        const u32* src = we + ((size_t)((s2 * 9 + tap2) * COUT + og * COUTB)) * KSEG;
        for (int i = tid; i < COUTB * (KSEG / 4); i += 256) {
            int o = i / (KSEG / 4), w4 = i - o * (KSEG / 4);
            cpasync16(dstb + (u32)((o * BP + w4 * 4) * 4), src + (size_t)o * KSEG + w4 * 4);
        }
        cp_commit();
    };

    stageA(0);
    issueB(0);

    #pragma unroll 1
    for (int it = 0; it < 27; ++it) {
        int si = it / 9, tap = it - 9 * si;
        cp_wait0();
        __syncthreads();
        if (it == 18) stageA(KSEG);
        if (it < 26) issueB(it + 1);
        if (it == 18) __syncthreads();
        int ty = tap / 3, tx = tap - 3 * ty;
        int arow = arow0 + ty * 34 + tx;
        u32 aAddr = saBase + (u32)(arow * AP) * 4u + akoff;
        u32 sbCur = sbB[it & 1];
        #pragma unroll
        for (int kc = 0; kc < KC; ++kc) {
            u32 a[2][4];
            ldsm4(a[0][0], a[0][1], a[0][2], a[0][3], aAddr + (u32)(kc * 32));
            ldsm4(a[1][0], a[1][1], a[1][2], a[1][3],
                  aAddr + (u32)(kc * 32) + (u32)(136 * AP * 4));
            #pragma unroll
            for (int j = 0; j < NF / 2; ++j) {
                u32 b0, b1, b2, b3;
                u32 bAddr = sbCur + (u32)(((j * 16 + brow) * BP + kc * 8) * 4) + bkoff;
                ldsm4(b0, b1, b2, b3, bAddr);
                mma16816(acc[0][2 * j],     a[0][0], a[0][1], a[0][2], a[0][3], b0, b1);
                mma16816(acc[0][2 * j + 1], a[0][0], a[0][1], a[0][2], a[0][3], b2, b3);
                mma16816(acc[1][2 * j],     a[1][0], a[1][1], a[1][2], a[1][3], b0, b1);
                mma16816(acc[1][2 * j + 1], a[1][0], a[1][1], a[1][2], a[1][3], b2, b3);
            }
        }
    }

    #pragma unroll 1
    for (int rb = 0; rb < 2; ++rb) {
        __syncthreads();
        int q0 = w * 16 + g;
        #pragma unroll
        for (int nf = 0; nf < NF; ++nf) {
            int cb = nf * 8 + 2 * tig;
            float d0 = s_d[cb], d1 = s_d[cb + 1];
            float b0 = s_b[cb], b1 = s_b[cb + 1];
            float y00 = acc[rb][nf][0] * d0 + b0, y01 = acc[rb][nf][1] * d1 + b1;
            float y10 = acc[rb][nf][2] * d0 + b0, y11 = acc[rb][nf][3] * d1 + b1;
            if (PASS == 1) {
                float m0 = s_m[cb], m1 = s_m[cb + 1];
                y00 = (y00 < 0.f ? 0.2f * y00 : y00) * m0;
                y01 = (y01 < 0.f ? 0.2f * y01 : y01) * m1;
                y10 = (y10 < 0.f ? 0.2f * y10 : y10) * m0;
                y11 = (y11 < 0.f ? 0.2f * y11 : y11) * m1;
            }
            sD[q0 * DP + cb] = y00; sD[q0 * DP + cb + 1] = y01;
            sD[(q0 + 8) * DP + cb] = y10; sD[(q0 + 8) * DP + cb + 1] = y11;
        }
        __syncthreads();
        if (PASS == 1) {
            for (int i = tid; i < 128 * 16; i += 256) {
                int q = i >> 4, t = i & 15;
                float4 y = *reinterpret_cast<const float4*>(sD + q * DP + 4 * t);
                u32 xh0 = packbf(y.x, y.y), xh1 = packbf(y.z, y.w);
                u32 xl0 = packbf(y.x - bfround(y.x), y.y - bfround(y.y));
                u32 xl1 = packbf(y.z - bfround(y.z), y.w - bfround(y.w));
                int gy = gy0 + rb * 4 + (q >> 5), gx = gx0 + (q & 31);
                u32* row = g_xa2 + (abase + (size_t)(gy + 1) * PDIM + gx + 1) * 128;
                int wj = og * 32 + 2 * t;
                *reinterpret_cast<u64*>(row + wj)      = (u64)xh0 | ((u64)xh1 << 32);
                *reinterpret_cast<u64*>(row + 64 + wj) = (u64)xl0 | ((u64)xl1 << 32);
            }
        } else {
            for (int i = tid; i < 32 * 128; i += 256) {
                int c = i >> 7, q = i & 127;
                float v = sD[q * DP + c];
                int gy = gy0 + rb * 4 + (q >> 5), gx = gx0 + (q & 31);
                g_tok[((size_t)bb * CH + c) * NPIX + gy * 256 + gx] = v;
            }
        }
    }
}

// ---------------------------------------------------------------------------
// Recon: row-separable, atomic-free gather-by-column (proven R14).
// ---------------------------------------------------------------------------
__global__ void __launch_bounds__(256) recon_kernel(
    const float* __restrict__ coords, float* __restrict__ out, ResArr R)
{
    __shared__ float smv0[256], smv1[256], smcx[256];
    int j = blockIdx.x & 255, b = blockIdx.x >> 8;
    int i = threadIdx.x;
    size_t pbase = (size_t)b * NPIX + (size_t)j * 256;
    smcx[i] = coords[(pbase + i) * 2 + 0];
    float cy = coords[pbase * 2 + 1];          // constant across the row

    #pragma unroll 1
    for (int l = 0; l < 16; ++l) {
        int Rl = R.r[l];
        float rf = (float)Rl;
        __syncthreads();
        smv0[i] = g_tok[(((size_t)(b * 32 + 2 * l))     << 16) + j * 256 + i];
        smv1[i] = g_tok[(((size_t)(b * 32 + 2 * l + 1)) << 16) + j * 256 + i];
        __syncthreads();
        float py = cy * rf;
        float fl = floorf(py);
        float fy = py - fl;
        u32 y0 = (u32)fl;
        u32 hy0 = y0 * PRIME, hy1 = (y0 + 1u) * PRIME;
        float wy0 = 1.f - fy;
        float* ob = out + ((size_t)(b * 16 + l) << 17);
        for (int k = i; k <= Rl; k += 256) {
            int lo = (int)((k - 1) * 256.f / rf) - 2; if (lo < 0) lo = 0;
            int hi = (int)((k + 1) * 256.f / rf) + 2; if (hi > 255) hi = 255;
            float t0 = 0.f, t1 = 0.f;
            for (int ii = lo; ii <= hi; ++ii) {
                float px = smcx[ii] * rf;
                float f0 = floorf(px);
                int x0 = (int)f0;
                float fx = px - f0;
                float wv = (x0 == k) ? (1.f - fx) : ((x0 == k - 1) ? fx : 0.f);
                t0 += wv * smv0[ii];
                t1 += wv * smv1[ii];
            }
            u32 h0 = ((u32)k ^ hy0) & 65535u;
            u32 h1 = ((u32)k ^ hy1) & 65535u;
            red2(ob + 2 * h0, wy0 * t0, wy0 * t1);
            red2(ob + 2 * h1, fy * t0,  fy * t1);
        }
    }
}

extern "C" void kernel_launch(void* const* d_in, const int* in_sizes, int n_in,
                              void* d_out, int out_size)
{
    const float* inputs = (const float*)d_in[0];
    const float* s      = (const float*)d_in[1];
    const float* coords = (const float*)d_in[2];
    const float* w1_aff = (const float*)d_in[3];
    const float* b1_aff = (const float*)d_in[4];
    const float* w1     = (const float*)d_in[5];
    const float* b1     = (const float*)d_in[6];
    const float* w2_aff = (const float*)d_in[7];
    const float* b2_aff = (const float*)d_in[8];
    const float* w2     = (const float*)d_in[9];
    const float* b2     = (const float*)d_in[10];
    float* out = (float*)d_out;

    ResArr R;
    double bb = exp((log(256.0) - log(16.0)) / 15.0);
    for (int l = 0; l < 16; ++l)
        R.r[l] = (int)floor(16.0 * pow(bb, (double)l));

    const int SM1 = (340 * 20 + 2 * 64 * 20) * 4;   // 37440
    const int SM2 = (340 * 68 + 2 * 32 * 68) * 4;   // 109888
    cudaFuncSetAttribute(convmma_kernel<1>, cudaFuncAttributeMaxDynamicSharedMemorySize, SM1);
    cudaFuncSetAttribute(convmma_kernel<2>, cudaFuncAttributeMaxDynamicSharedMemorySize, SM2);

    cudaMemsetAsync(d_out, 0, (size_t)out_size * sizeof(float));

    styles_kernel<<<440 + BATCH * 1032, 256>>>(s, w1_aff, b1_aff, w2_aff, b2_aff, w1, w2);
    retrieve_kernel<<<2048 + 6, 256>>>(inputs, coords, w1, w2, R);

    dim3 cg1(8, 32, BATCH * 2);
    convmma_kernel<1><<<cg1, 256, SM1>>>(b1);
    dim3 cg2(8, 32, BATCH);
    convmma_kernel<2><<<cg2, 256, SM2>>>(b2);

    recon_kernel<<<BATCH * 256, 256>>>(coords, out, R);
}

// round 17
// speedup vs baseline: 1.0998x; 1.0156x over previous
#include <cuda_runtime.h>
#include <cuda_bf16.h>
#include <math.h>

#define TABLE_NUM 16
#define STYLE_DIM 512
#define CH 32
#define CMID 128
#define BATCH 8
#define NPIX 65536
#define PRIME 2654435761u
#define PDIM 258
#define PPIX (PDIM*PDIM)

typedef unsigned long long u64;
typedef unsigned int u32;

struct ResArr { int r[16]; };

__device__ float g_tok[(size_t)BATCH * CH * NPIX];
__device__ u32 g_xa1[(size_t)BATCH * PPIX * 32];    // padded [xh16|xl16] u32/px
__device__ u32 g_xa2[(size_t)BATCH * PPIX * 128];   // padded [xh64|xl64] u32/px
__device__ u32 g_w1e[3 * 9 * 128 * 16];             // seg0,1=wh seg2=wl
__device__ u32 g_w2e[3 * 9 * 32 * 64];
__device__ float g_st1[BATCH * CH];
__device__ float g_st2[BATCH * CMID];
__device__ float g_d1 [BATCH * CMID];
__device__ float g_d2 [BATCH * CH];

__device__ __forceinline__ float bfround(float v) {
    return __bfloat162float(__float2bfloat16_rn(v));
}
__device__ __forceinline__ u32 packbf(float lo, float hi) {
    u32 l = (u32)__bfloat16_as_ushort(__float2bfloat16_rn(lo));
    u32 h = (u32)__bfloat16_as_ushort(__float2bfloat16_rn(hi));
    return l | (h << 16);
}
__device__ __forceinline__ void mma16816(float* c, u32 a0, u32 a1, u32 a2, u32 a3,
                                         u32 b0, u32 b1) {
    asm volatile(
        "mma.sync.aligned.m16n8k16.row.col.f32.bf16.bf16.f32 "
        "{%0,%1,%2,%3}, {%4,%5,%6,%7}, {%8,%9}, {%0,%1,%2,%3};"
        : "+f"(c[0]), "+f"(c[1]), "+f"(c[2]), "+f"(c[3])
        : "r"(a0), "r"(a1), "r"(a2), "r"(a3), "r"(b0), "r"(b1));
}
__device__ __forceinline__ void ldsm4(u32& r0, u32& r1, u32& r2, u32& r3, u32 addr) {
    asm volatile("ldmatrix.sync.aligned.m8n8.x4.shared.b16 {%0,%1,%2,%3}, [%4];"
                 : "=r"(r0), "=r"(r1), "=r"(r2), "=r"(r3) : "r"(addr));
}
__device__ __forceinline__ u32 smem_u32(const void* p) {
    return (u32)__cvta_generic_to_shared(p);
}
__device__ __forceinline__ void cpasync16(u32 dst, const void* src) {
    asm volatile("cp.async.cg.shared.global [%0], [%1], 16;" :: "r"(dst), "l"(src));
}
__device__ __forceinline__ void cp_commit() {
    asm volatile("cp.async.commit_group;" ::: "memory");
}
__device__ __forceinline__ void cp_wait0() {
    asm volatile("cp.async.wait_group 0;" ::: "memory");
}
__device__ __forceinline__ void red2(float* p, float a, float b) {
    asm volatile("red.global.add.v2.f32 [%0], {%1, %2};"
                 :: "l"(p), "f"(a), "f"(b) : "memory");
}

// styles (blocks 0-7) | weight split (8-439) | borders (440+)
__global__ void styles_kernel(const float* __restrict__ s,
                              const float* __restrict__ w1a, const float* __restrict__ b1a,
                              const float* __restrict__ w2a, const float* __restrict__ b2a,
                              const float* __restrict__ w1,  const float* __restrict__ w2)
{
    int blk = blockIdx.x;
    if (blk < 8) {
        int b = blk, t = threadIdx.x;
        float inv = 1.0f / sqrtf(512.0f);
        const float* sb = s + b * STYLE_DIM;
        if (t < CH) {
            float acc = 0.f;
            for (int k = 0; k < STYLE_DIM; ++k) acc += sb[k] * (w1a[k * CH + t] * inv);
            g_st1[b * CH + t] = acc + b1a[t];
        } else if (t < CH + CMID) {
            int c = t - CH;
            float acc = 0.f;
            for (int k = 0; k < STYLE_DIM; ++k) acc += sb[k] * (w2a[k * CMID + c] * inv);
            g_st2[b * CMID + c] = acc + b2a[c];
        }
    } else if (blk < 440) {
        int i = (blk - 8) * 256 + threadIdx.x;
        if (i < 3 * 9 * 128 * 16) {
            int j = i & 15, rest = i >> 4;
            int o = rest & 127; rest >>= 7;
            int t = rest % 9, sI = rest / 9;
            float va = w1[((size_t)o * 32 + 2 * j) * 9 + t];
            float vb = w1[((size_t)o * 32 + 2 * j + 1) * 9 + t];
            if (sI == 2) { va -= bfround(va); vb -= bfround(vb); }
            g_w1e[i] = packbf(va, vb);
        } else {
            int i2 = i - 3 * 9 * 128 * 16;
            if (i2 < 3 * 9 * 32 * 64) {
                int j = i2 & 63, rest = i2 >> 6;
                int o = rest & 31; rest >>= 5;
                int t = rest % 9, sI = rest / 9;
                float va = w2[((size_t)o * 128 + 2 * j) * 9 + t];
                float vb = w2[((size_t)o * 128 + 2 * j + 1) * 9 + t];
                if (sI == 2) { va -= bfround(va); vb -= bfround(vb); }
                g_w2e[i2] = packbf(va, vb);
            }
        }
    } else {
        int cell = blk - 440;
        int b = cell / 1032, e = cell % 1032;
        int gy, gx;
        if      (e < 258) { gy = 0;       gx = e; }
        else if (e < 516) { gy = 257;     gx = e - 258; }
        else if (e < 774) { gy = e - 516; gx = 0; }
        else              { gy = e - 774; gx = 257; }
        size_t p = (size_t)b * PPIX + (size_t)gy * PDIM + gx;
        int t = threadIdx.x;
        if (t < 32)       g_xa1[p * 32 + t] = 0u;
        else if (t < 160) g_xa2[p * 128 + (t - 32)] = 0u;
    }
}

// retrieve (blocks 0-2047, fused with split) | demod (blocks 2048-2053)
__global__ void __launch_bounds__(256) retrieve_kernel(
    const float* __restrict__ tables, const float* __restrict__ coords,
    const float* __restrict__ w1, const float* __restrict__ w2, ResArr R)
{
    if (blockIdx.x >= 2048) {
        int i = (blockIdx.x - 2048) * 256 + threadIdx.x;
        if (i < BATCH * CMID) {
            int b = i >> 7, o = i & 127;
            float acc = 0.f;
            for (int c = 0; c < CH; ++c) {
                float st = g_st1[b * CH + c], wq = 0.f;
                const float* wp = w1 + ((size_t)o * CH + c) * 9;
                #pragma unroll
                for (int t = 0; t < 9; ++t) { float v = wp[t]; wq += v * v; }
                acc += wq * st * st;
            }
            g_d1[i] = rsqrtf(acc + 1e-8f);
        } else if (i < BATCH * CMID + BATCH * CH) {
            int j = i - BATCH * CMID;
            int b = j >> 5, o = j & 31;
            float acc = 0.f;
            for (int c = 0; c < CMID; ++c) {
                float st = g_st2[b * CMID + c], wq = 0.f;
                const float* wp = w2 + ((size_t)o * CMID + c) * 9;
                #pragma unroll
                for (int t = 0; t < 9; ++t) { float v = wp[t]; wq += v * v; }
                acc += wq * st * st;
            }
            g_d2[j] = rsqrtf(acc + 1e-8f);
        }
        return;
    }
    int idx = blockIdx.x * 256 + threadIdx.x;
    int b = idx >> 16, p = idx & 65535;
    __shared__ float s1[CH];
    if (threadIdx.x < CH) s1[threadIdx.x] = g_st1[b * CH + threadIdx.x];
    __syncthreads();
    float cx = coords[((size_t)b * NPIX + p) * 2 + 0];
    float cy = coords[((size_t)b * NPIX + p) * 2 + 1];
    u32 ov[32];
    #pragma unroll
    for (int l = 0; l < 16; ++l) {
        float rf = (float)R.r[l];
        float px = cx * rf, py = cy * rf;
        float fx0 = floorf(px), fy0 = floorf(py);
        float fx = px - fx0, fy = py - fy0;
        unsigned x0 = (unsigned)fx0, y0 = (unsigned)fy0;
        unsigned hy0 = y0 * PRIME, hy1 = (y0 + 1u) * PRIME;
        unsigned h00 = (x0 ^ hy0) & 65535u, h10 = ((x0 + 1u) ^ hy0) & 65535u;
        unsigned h01 = (x0 ^ hy1) & 65535u, h11 = ((x0 + 1u) ^ hy1) & 65535u;
        const float2* tab = reinterpret_cast<const float2*>(tables) + ((size_t)(b * 16 + l) << 16);
        float2 f00 = __ldg(tab + h00), f10 = __ldg(tab + h10);
        float2 f01 = __ldg(tab + h01), f11 = __ldg(tab + h11);
        float w00 = (1.f - fx) * (1.f - fy), w10 = fx * (1.f - fy);
        float w01 = (1.f - fx) * fy,         w11 = fx * fy;
        float e0 = (w00 * f00.x + w10 * f10.x + w01 * f01.x + w11 * f11.x) * s1[2 * l];
        float e1 = (w00 * f00.y + w10 * f10.y + w01 * f01.y + w11 * f11.y) * s1[2 * l + 1];
        ov[l]      = packbf(e0, e1);
        ov[16 + l] = packbf(e0 - bfround(e0), e1 - bfround(e1));
    }
    int gy = p >> 8, gx = p & 255;
    u32* row = g_xa1 + ((size_t)b * PPIX + (size_t)(gy + 1) * PDIM + gx + 1) * 32;
    #pragma unroll
    for (int j = 0; j < 8; ++j)
        *reinterpret_cast<uint4*>(row + 4 * j) =
            make_uint4(ov[4 * j], ov[4 * j + 1], ov[4 * j + 2], ov[4 * j + 3]);
}

// conv1: proven R12 implicit-GEMM (depth-1 cp.async B double buffer)
__global__ void __launch_bounds__(256, 2) conv1_kernel(const float* __restrict__ bias)
{
    constexpr int AP = 20, BP = 20, KSEG = 16, KROW = 32;
    constexpr int KC = 2, NF = 8, DP = 68;
    constexpr int ASZ = 340 * AP, BSZ = 64 * BP;

    extern __shared__ float smf[];
    u32* sA = reinterpret_cast<u32*>(smf);
    u32* sB0 = sA + ASZ;
    u32* sB1 = sA + ASZ + BSZ;
    float* sD = smf;
    __shared__ float s_d[64], s_b[64], s_m[64];

    int zz = blockIdx.z;
    int bb = zz >> 1, og = zz & 1;
    int gy0 = blockIdx.y * 8, gx0 = blockIdx.x * 32;
    int tid = threadIdx.x;
    int w = tid >> 5, lane = tid & 31, g = lane >> 2, tig = lane & 3;
    int qrow = w >> 1;
    int lane7 = lane & 7, l8 = (lane >> 3) & 1, l16 = (lane >> 4) & 1;

    if (tid < 64) {
        s_d[tid] = g_d1[bb * 128 + og * 64 + tid];
        s_b[tid] = bias[og * 64 + tid];
        s_m[tid] = g_st2[bb * CMID + og * 64 + tid] * 1.4142135623730951f;
    }

    u32 saBase = smem_u32(sA);
    u32 sbB[2] = { smem_u32(sB0), smem_u32(sB1) };
    int arow0 = qrow * 34 + (w & 1) * 16 + lane7 + l8 * 8;
    u32 akoff = (u32)(l16 * 16);
    int brow = lane7 + l16 * 8;
    u32 bkoff = (u32)(l8 * 16);

    size_t abase = (size_t)bb * PPIX;
    float acc[2][NF][4];
    #pragma unroll
    for (int rb = 0; rb < 2; ++rb)
        #pragma unroll
        for (int n = 0; n < NF; ++n)
            #pragma unroll
            for (int q = 0; q < 4; ++q) acc[rb][n][q] = 0.f;

    auto stageA = [&](int segoff) {
        for (int i = tid; i < 340 * (KSEG / 4); i += 256) {
            int r = i / (KSEG / 4), w4 = i - r * (KSEG / 4);
            int sy = r / 34, sx = r - sy * 34;
            size_t p = abase + (size_t)(gy0 + sy) * PDIM + gx0 + sx;
            uint4 v = *reinterpret_cast<const uint4*>(g_xa1 + p * KROW + segoff + w4 * 4);
            *reinterpret_cast<uint4*>(sA + r * AP + w4 * 4) = v;
        }
    };
    auto issueB = [&](int it2) {
        int si2 = it2 / 9, tap2 = it2 - 9 * si2;
        int s2 = (si2 == 0) ? 0 : (si2 == 1) ? 2 : 1;
        u32 dstb = sbB[it2 & 1];
        const u32* src = g_w1e + ((size_t)((s2 * 9 + tap2) * 128 + og * 64)) * KSEG;
        for (int i = tid; i < 64 * (KSEG / 4); i += 256) {
            int o = i / (KSEG / 4), w4 = i - o * (KSEG / 4);
            cpasync16(dstb + (u32)((o * BP + w4 * 4) * 4), src + (size_t)o * KSEG + w4 * 4);
        }
        cp_commit();
    };

    stageA(0);
    issueB(0);

    #pragma unroll 1
    for (int it = 0; it < 27; ++it) {
        int si = it / 9, tap = it - 9 * si;
        cp_wait0();
        __syncthreads();
        if (it == 18) stageA(KSEG);
        if (it < 26) issueB(it + 1);
        if (it == 18) __syncthreads();
        int ty = tap / 3, tx = tap - 3 * ty;
        int arow = arow0 + ty * 34 + tx;
        u32 aAddr = saBase + (u32)(arow * AP) * 4u + akoff;
        u32 sbCur = sbB[it & 1];
        #pragma unroll
        for (int kc = 0; kc < KC; ++kc) {
            u32 a[2][4];
            ldsm4(a[0][0], a[0][1], a[0][2], a[0][3], aAddr + (u32)(kc * 32));
            ldsm4(a[1][0], a[1][1], a[1][2], a[1][3],
                  aAddr + (u32)(kc * 32) + (u32)(136 * AP * 4));
            #pragma unroll
            for (int j = 0; j < NF / 2; ++j) {
                u32 b0, b1, b2, b3;
                u32 bAddr = sbCur + (u32)(((j * 16 + brow) * BP + kc * 8) * 4) + bkoff;
                ldsm4(b0, b1, b2, b3, bAddr);
                mma16816(acc[0][2 * j],     a[0][0], a[0][1], a[0][2], a[0][3], b0, b1);
                mma16816(acc[0][2 * j + 1], a[0][0], a[0][1], a[0][2], a[0][3], b2, b3);
                mma16816(acc[1][2 * j],     a[1][0], a[1][1], a[1][2], a[1][3], b0, b1);
                mma16816(acc[1][2 * j + 1], a[1][0], a[1][1], a[1][2], a[1][3], b2, b3);
            }
        }
    }

    #pragma unroll 1
    for (int rb = 0; rb < 2; ++rb) {
        __syncthreads();
        int q0 = w * 16 + g;
        #pragma unroll
        for (int nf = 0; nf < NF; ++nf) {
            int cb = nf * 8 + 2 * tig;
            float d0 = s_d[cb], d1 = s_d[cb + 1];
            float b0 = s_b[cb], b1 = s_b[cb + 1];
            float m0 = s_m[cb], m1 = s_m[cb + 1];
            float y00 = acc[rb][nf][0] * d0 + b0, y01 = acc[rb][nf][1] * d1 + b1;
            float y10 = acc[rb][nf][2] * d0 + b0, y11 = acc[rb][nf][3] * d1 + b1;
            y00 = (y00 < 0.f ? 0.2f * y00 : y00) * m0;
            y01 = (y01 < 0.f ? 0.2f * y01 : y01) * m1;
            y10 = (y10 < 0.f ? 0.2f * y10 : y10) * m0;
            y11 = (y11 < 0.f ? 0.2f * y11 : y11) * m1;
            sD[q0 * DP + cb] = y00; sD[q0 * DP + cb + 1] = y01;
            sD[(q0 + 8) * DP + cb] = y10; sD[(q0 + 8) * DP + cb + 1] = y11;
        }
        __syncthreads();
        for (int i = tid; i < 128 * 16; i += 256) {
            int q = i >> 4, t = i & 15;
            float4 y = *reinterpret_cast<const float4*>(sD + q * DP + 4 * t);
            u32 xh0 = packbf(y.x, y.y), xh1 = packbf(y.z, y.w);
            u32 xl0 = packbf(y.x - bfround(y.x), y.y - bfround(y.y));
            u32 xl1 = packbf(y.z - bfround(y.z), y.w - bfround(y.w));
            int gy = gy0 + rb * 4 + (q >> 5), gx = gx0 + (q & 31);
            u32* row = g_xa2 + (abase + (size_t)(gy + 1) * PDIM + gx + 1) * 128;
            int wj = og * 32 + 2 * t;
            *reinterpret_cast<u64*>(row + wj)      = (u64)xh0 | ((u64)xh1 << 32);
            *reinterpret_cast<u64*>(row + 64 + wj) = (u64)xl0 | ((u64)xl1 << 32);
        }
    }
}

// conv2: R12 pipeline + kc-level fragment software pipelining (LDSM for kc+1
// issued before mma of kc -> hides ~30cyc smem latency under tensor work).
__global__ void __launch_bounds__(256, 2) conv2_kernel(const float* __restrict__ bias)
{
    constexpr int KSEG = 64, KROW = 128;
    constexpr int AP = 68, BP = 68;
    constexpr int KC = 8, DP = 36;
    constexpr int ASZ = 340 * AP, BSZ = 32 * BP;

    extern __shared__ float smf[];
    u32* sA = reinterpret_cast<u32*>(smf);
    u32* sB0 = sA + ASZ;
    u32* sB1 = sA + ASZ + BSZ;
    float* sD = smf;
    __shared__ float s_d[32], s_b[32];

    int bb = blockIdx.z;
    int gy0 = blockIdx.y * 8, gx0 = blockIdx.x * 32;
    int tid = threadIdx.x;
    int w = tid >> 5, lane = tid & 31, g = lane >> 2, tig = lane & 3;
    int qrow = w >> 1;
    int lane7 = lane & 7, l8 = (lane >> 3) & 1, l16 = (lane >> 4) & 1;

    if (tid < 32) {
        s_d[tid] = g_d2[bb * 32 + tid];
        s_b[tid] = bias[tid];
    }

    u32 saBase = smem_u32(sA);
    u32 sbB[2] = { smem_u32(sB0), smem_u32(sB1) };
    int arow0 = qrow * 34 + (w & 1) * 16 + lane7 + l8 * 8;
    u32 akoff = (u32)(l16 * 16);
    int brow = lane7 + l16 * 8;
    u32 bkoff = (u32)(l8 * 16);

    size_t abase = (size_t)bb * PPIX;
    float acc[2][4][4];
    #pragma unroll
    for (int rb = 0; rb < 2; ++rb)
        #pragma unroll
        for (int n = 0; n < 4; ++n)
            #pragma unroll
            for (int q = 0; q < 4; ++q) acc[rb][n][q] = 0.f;

    auto stageA = [&](int segoff) {
        for (int i = tid; i < 340 * (KSEG / 4); i += 256) {
            int r = i / (KSEG / 4), w4 = i - r * (KSEG / 4);
            int sy = r / 34, sx = r - sy * 34;
            size_t p = abase + (size_t)(gy0 + sy) * PDIM + gx0 + sx;
            uint4 v = *reinterpret_cast<const uint4*>(g_xa2 + p * KROW + segoff + w4 * 4);
            *reinterpret_cast<uint4*>(sA + r * AP + w4 * 4) = v;
        }
    };
    auto issueB = [&](int it2) {
        int si2 = it2 / 9, tap2 = it2 - 9 * si2;
        int s2 = (si2 == 0) ? 0 : (si2 == 1) ? 2 : 1;
        u32 dstb = sbB[it2 & 1];
        const u32* src = g_w2e + ((size_t)((s2 * 9 + tap2) * 32)) * KSEG;
        for (int i = tid; i < 32 * (KSEG / 4); i += 256) {
            int o = i / (KSEG / 4), w4 = i - o * (KSEG / 4);
            cpasync16(dstb + (u32)((o * BP + w4 * 4) * 4), src + (size_t)o * KSEG + w4 * 4);
        }
        cp_commit();
    };

    stageA(0);
    issueB(0);

    #pragma unroll 1
    for (int it = 0; it < 27; ++it) {
        cp_wait0();
        __syncthreads();
        if (it == 18) stageA(KSEG);
        if (it < 26) issueB(it + 1);
        if (it == 18) __syncthreads();
        int si = it / 9, tap = it - 9 * si;
        int ty = tap / 3, tx = tap - 3 * ty;
        int arow = arow0 + ty * 34 + tx;
        u32 aAddr = saBase + (u32)(arow * AP) * 4u + akoff;
        u32 bBase = sbB[it & 1] + (u32)(brow * BP * 4) + bkoff;

        // kc-level software pipeline: fragments double-buffered
        u32 a[2][2][4], bf[2][2][4];
        ldsm4(a[0][0][0], a[0][0][1], a[0][0][2], a[0][0][3], aAddr);
        ldsm4(a[0][1][0], a[0][1][1], a[0][1][2], a[0][1][3], aAddr + (u32)(136 * AP * 4));
        ldsm4(bf[0][0][0], bf[0][0][1], bf[0][0][2], bf[0][0][3], bBase);
        ldsm4(bf[0][1][0], bf[0][1][1], bf[0][1][2], bf[0][1][3], bBase + (u32)(16 * BP * 4));
        #pragma unroll
        for (int kc = 0; kc < KC; ++kc) {
            int cur = kc & 1, nxt = cur ^ 1;
            if (kc < KC - 1) {
                u32 aN = aAddr + (u32)((kc + 1) * 32);
                u32 bN = bBase + (u32)((kc + 1) * 32);
                ldsm4(a[nxt][0][0], a[nxt][0][1], a[nxt][0][2], a[nxt][0][3], aN);
                ldsm4(a[nxt][1][0], a[nxt][1][1], a[nxt][1][2], a[nxt][1][3],
                      aN + (u32)(136 * AP * 4));
                ldsm4(bf[nxt][0][0], bf[nxt][0][1], bf[nxt][0][2], bf[nxt][0][3], bN);
                ldsm4(bf[nxt][1][0], bf[nxt][1][1], bf[nxt][1][2], bf[nxt][1][3],
                      bN + (u32)(16 * BP * 4));
            }
            #pragma unroll
            for (int j = 0; j < 2; ++j) {
                mma16816(acc[0][2 * j],     a[cur][0][0], a[cur][0][1], a[cur][0][2], a[cur][0][3],
                         bf[cur][j][0], bf[cur][j][1]);
                mma16816(acc[0][2 * j + 1], a[cur][0][0], a[cur][0][1], a[cur][0][2], a[cur][0][3],
                         bf[cur][j][2], bf[cur][j][3]);
                mma16816(acc[1][2 * j],     a[cur][1][0], a[cur][1][1], a[cur][1][2], a[cur][1][3],
                         bf[cur][j][0], bf[cur][j][1]);
                mma16816(acc[1][2 * j + 1], a[cur][1][0], a[cur][1][1], a[cur][1][2], a[cur][1][3],
                         bf[cur][j][2], bf[cur][j][3]);
            }
        }
    }

    #pragma unroll 1
    for (int rb = 0; rb < 2; ++rb) {
        __syncthreads();
        int q0 = w * 16 + g;
        #pragma unroll
        for (int nf = 0; nf < 4; ++nf) {
            int cb = nf * 8 + 2 * tig;
            float d0 = s_d[cb], d1 = s_d[cb + 1];
            float b0 = s_b[cb], b1 = s_b[cb + 1];
            sD[q0 * DP + cb]       = acc[rb][nf][0] * d0 + b0;
            sD[q0 * DP + cb + 1]   = acc[rb][nf][1] * d1 + b1;
            sD[(q0 + 8) * DP + cb]     = acc[rb][nf][2] * d0 + b0;
            sD[(q0 + 8) * DP + cb + 1] = acc[rb][nf][3] * d1 + b1;
        }
        __syncthreads();
        for (int i = tid; i < 32 * 128; i += 256) {
            int c = i >> 7, q = i & 127;
            float v = sD[q * DP + c];
            int gy = gy0 + rb * 4 + (q >> 5), gx = gx0 + (q & 31);
            g_tok[((size_t)bb * CH + c) * NPIX + gy * 256 + gx] = v;
        }
    }
}

// ---------------------------------------------------------------------------
// Recon: row-separable, atomic-free gather-by-column (proven R14).
// ---------------------------------------------------------------------------
__global__ void __launch_bounds__(256) recon_kernel(
    const float* __restrict__ coords, float* __restrict__ out, ResArr R)
{
    __shared__ float smv0[256], smv1[256], smcx[256];
    int j = blockIdx.x & 255, b = blockIdx.x >> 8;
    int i = threadIdx.x;
    size_t pbase = (size_t)b * NPIX + (size_t)j * 256;
    smcx[i] = coords[(pbase + i) * 2 + 0];
    float cy = coords[pbase * 2 + 1];          // constant across the row

    #pragma unroll 1
    for (int l = 0; l < 16; ++l) {
        int Rl = R.r[l];
        float rf = (float)Rl;
        __syncthreads();
        smv0[i] = g_tok[(((size_t)(b * 32 + 2 * l))     << 16) + j * 256 + i];
        smv1[i] = g_tok[(((size_t)(b * 32 + 2 * l + 1)) << 16) + j * 256 + i];
        __syncthreads();
        float py = cy * rf;
        float fl = floorf(py);
        float fy = py - fl;
        u32 y0 = (u32)fl;
        u32 hy0 = y0 * PRIME, hy1 = (y0 + 1u) * PRIME;
        float wy0 = 1.f - fy;
        float* ob = out + ((size_t)(b * 16 + l) << 17);
        for (int k = i; k <= Rl; k += 256) {
            int lo = (int)((k - 1) * 256.f / rf) - 2; if (lo < 0) lo = 0;
            int hi = (int)((k + 1) * 256.f / rf) + 2; if (hi > 255) hi = 255;
            float t0 = 0.f, t1 = 0.f;
            for (int ii = lo; ii <= hi; ++ii) {
                float px = smcx[ii] * rf;
                float f0 = floorf(px);
                int x0 = (int)f0;
                float fx = px - f0;
                float wv = (x0 == k) ? (1.f - fx) : ((x0 == k - 1) ? fx : 0.f);
                t0 += wv * smv0[ii];
                t1 += wv * smv1[ii];
            }
            u32 h0 = ((u32)k ^ hy0) & 65535u;
            u32 h1 = ((u32)k ^ hy1) & 65535u;
            red2(ob + 2 * h0, wy0 * t0, wy0 * t1);
            red2(ob + 2 * h1, fy * t0,  fy * t1);
        }
    }
}

extern "C" void kernel_launch(void* const* d_in, const int* in_sizes, int n_in,
                              void* d_out, int out_size)
{
    const float* inputs = (const float*)d_in[0];
    const float* s      = (const float*)d_in[1];
    const float* coords = (const float*)d_in[2];
    const float* w1_aff = (const float*)d_in[3];
    const float* b1_aff = (const float*)d_in[4];
    const float* w1     = (const float*)d_in[5];
    const float* b1     = (const float*)d_in[6];
    const float* w2_aff = (const float*)d_in[7];
    const float* b2_aff = (const float*)d_in[8];
    const float* w2     = (const float*)d_in[9];
    const float* b2     = (const float*)d_in[10];
    float* out = (float*)d_out;

    ResArr R;
    double bb = exp((log(256.0) - log(16.0)) / 15.0);
    for (int l = 0; l < 16; ++l)
        R.r[l] = (int)floor(16.0 * pow(bb, (double)l));

    const int SM1 = (340 * 20 + 2 * 64 * 20) * 4;   // 37440
    const int SM2 = (340 * 68 + 2 * 32 * 68) * 4;   // 109888
    cudaFuncSetAttribute(conv1_kernel, cudaFuncAttributeMaxDynamicSharedMemorySize, SM1);
    cudaFuncSetAttribute(conv2_kernel, cudaFuncAttributeMaxDynamicSharedMemorySize, SM2);

    cudaMemsetAsync(d_out, 0, (size_t)out_size * sizeof(float));

    styles_kernel<<<440 + BATCH * 1032, 256>>>(s, w1_aff, b1_aff, w2_aff, b2_aff, w1, w2);
    retrieve_kernel<<<2048 + 6, 256>>>(inputs, coords, w1, w2, R);

    dim3 cg1(8, 32, BATCH * 2);
    conv1_kernel<<<cg1, 256, SM1>>>(b1);
    dim3 cg2(8, 32, BATCH);
    conv2_kernel<<<cg2, 256, SM2>>>(b2);

    recon_kernel<<<BATCH * 256, 256>>>(coords, out, R);
}